// round 1
// baseline (speedup 1.0000x reference)
#include <cuda_runtime.h>

#define T_FULL 529
#define N_NEU  1024
#define N_CH   512
#define T_IN   512
#define N_B    16
#define TBLK   16
#define THETA  25.6f
#define BIASV  12.8f

// wT[i][n] = weight[n][i]  (2 MB, L2-resident)
__device__ float g_wT[N_CH * N_NEU];
// per-(b,t) argmax value/index (argmax is depression-independent since C=1
// depression is uniform across neurons)
__device__ float g_val[N_B][544];
__device__ int   g_idx[N_B][544];

__global__ void transpose_kernel(const float* __restrict__ w) {
    int idx = blockIdx.x * blockDim.x + threadIdx.x;
    if (idx < N_CH * N_NEU) {
        int i = idx >> 10;        // channel
        int n = idx & 1023;       // neuron
        g_wT[idx] = w[n * N_CH + i];
    }
}

// One block = (batch b, t in [t0, t0+16)). 1024 threads, thread = neuron n.
__global__ void __launch_bounds__(1024) pot_kernel(const float* __restrict__ x) {
    // per-warp spike-list segments: 32 warps x 128 entries
    __shared__ unsigned int s_list[32 * 128];
    __shared__ int s_cnt[32];
    __shared__ float s_rv[32];
    __shared__ int   s_ri[32];

    const int b   = blockIdx.y;
    const int t0  = blockIdx.x * TBLK;
    const int tid = threadIdx.x;
    const int wid = tid >> 5;
    const int lane = tid & 31;
    const int n = tid;

    // ---- Phase 1: deterministic spike compaction (no atomics) ----
    // Window entries e in [0, 512*64): i = e>>6, dts = e&63, ts = t0-32+dts.
    // Spike at ts contributes to t in [ts-15, ts+32]; for this block's t-range
    // only dts <= 61 matters.
    {
        const float* xb = x + b * (N_CH * T_IN);
        int cnt = 0;
        #pragma unroll 4
        for (int it = 0; it < 32; it++) {
            int e   = wid * 1024 + it * 32 + lane;
            int i   = e >> 6;
            int dts = e & 63;
            int ts  = t0 - 32 + dts;
            bool sp = (dts <= 61) && (ts >= 0) && (ts < T_IN) &&
                      (xb[i * T_IN + ts] != 0.0f);
            unsigned int m = __ballot_sync(0xffffffffu, sp);
            if (sp) {
                int ofs = cnt + __popc(m & ((1u << lane) - 1u));
                if (ofs < 128) s_list[wid * 128 + ofs] = ((unsigned)i << 6) | (unsigned)dts;
            }
            cnt += __popc(m);
        }
        if (lane == 0) s_cnt[wid] = min(cnt, 128);
    }
    __syncthreads();

    // ---- Phase 2: accumulate potentials ----
    float acc[TBLK];
    #pragma unroll
    for (int k = 0; k < TBLK; k++) acc[k] = 0.0f;

    for (int seg = 0; seg < 32; seg++) {
        const int cnt = s_cnt[seg];
        for (int s = 0; s < cnt; s++) {
            unsigned int p = s_list[seg * 128 + s];   // smem broadcast
            int i   = (int)(p >> 6);
            int dts = (int)(p & 63u);
            float w = g_wT[i * N_NEU + n];            // coalesced, L1/L2 hit
            // j = k + (47 - dts);  kernel value:
            //   f = max(0, min(j/16, 1.5w - j/32))
            // formula is naturally 0 for j<=0 and j>=48 (w<=1), so no bounds.
            float u0  = (float)(47 - dts) * 0.0625f;  // j/16 at k=0
            float w15 = 1.5f * w;
            #pragma unroll
            for (int k = 0; k < TBLK; k++) {
                float uk = u0 + (float)k * 0.0625f;   // j/16
                float v  = fmaf(uk, -0.5f, w15);      // 1.5w - j/32
                float f  = fminf(uk, v);
                f = fmaxf(f, 0.0f);
                acc[k] += f;
            }
        }
    }

    // ---- Phase 3: per-t argmax over n (epilogue block reduce) ----
    for (int k = 0; k < TBLK; k++) {
        float v  = acc[k] + BIASV;
        int   bi = n;
        #pragma unroll
        for (int o = 16; o > 0; o >>= 1) {
            float v2 = __shfl_down_sync(0xffffffffu, v, o);
            int   i2 = __shfl_down_sync(0xffffffffu, bi, o);
            if (v2 > v || (v2 == v && i2 < bi)) { v = v2; bi = i2; }
        }
        if (lane == 0) { s_rv[wid] = v; s_ri[wid] = bi; }
        __syncthreads();
        if (tid < 32) {
            v = s_rv[tid]; bi = s_ri[tid];
            #pragma unroll
            for (int o = 16; o > 0; o >>= 1) {
                float v2 = __shfl_down_sync(0xffffffffu, v, o);
                int   i2 = __shfl_down_sync(0xffffffffu, bi, o);
                if (v2 > v || (v2 == v && i2 < bi)) { v = v2; bi = i2; }
            }
            int t = t0 + k;
            if (tid == 0 && t < T_FULL) { g_val[b][t] = v; g_idx[b][t] = bi; }
        }
        __syncthreads();
    }
}

// Sequential WTA scan: depression is uniform per batch -> a scalar skip counter.
__global__ void wta_kernel(float* __restrict__ out) {
    int b = threadIdx.x;
    if (b >= N_B) return;
    float* ob = out + (size_t)b * N_NEU * T_FULL;
    int skip = 0;
    for (int t = 0; t < T_FULL; t++) {
        if (skip > 0) { skip--; continue; }
        if (g_val[b][t] > THETA) {
            ob[(size_t)g_idx[b][t] * T_FULL + t] = 1.0f;
            skip = 47;   // clip(dep+48-1) = 47 masked steps
        }
    }
}

extern "C" void kernel_launch(void* const* d_in, const int* in_sizes, int n_in,
                              void* d_out, int out_size) {
    const float* x;
    const float* w;
    if (in_sizes[0] == N_B * N_CH * T_IN) { x = (const float*)d_in[0]; w = (const float*)d_in[1]; }
    else                                  { x = (const float*)d_in[1]; w = (const float*)d_in[0]; }
    float* out = (float*)d_out;

    cudaMemsetAsync(d_out, 0, (size_t)out_size * sizeof(float), 0);
    transpose_kernel<<<(N_CH * N_NEU + 255) / 256, 256>>>(w);
    dim3 grid((T_FULL + TBLK - 1) / TBLK, N_B);   // 34 x 16
    pot_kernel<<<grid, 1024>>>(x);
    wta_kernel<<<1, 16>>>(out);
}

// round 2
// speedup vs baseline: 2.5413x; 2.5413x over previous
#include <cuda_runtime.h>

#define T_FULL 529
#define N_NEU  1024
#define N_CH   512
#define T_IN   512
#define N_B    16
#define THETA  25.6f
#define BIASV  12.8f

#define NCHUNK 8          // ts chunks of 64
#define CAP    2560       // max spikes per (batch, chunk); expected ~1638
#define NC     32         // neurons per block (= #banks -> conflict-free scatter)
#define NBLK   (N_NEU/NC) // 32
#define DW     564        // deposit array length over t (need >= 561)
#define SEGL   71         // scan segment length (8*71 >= 564)

__device__ int   g_scnt[N_B][NCHUNK];
__device__ int   g_spk[N_B][NCHUNK][CAP];
__device__ float g_pd[5][N_CH * N_NEU];   // deposit values, [k][i*1024+n]
__device__ int   g_pp[N_CH * N_NEU];      // packed element offsets a*32 | (b*32<<16)
__device__ float g_cval[N_B][NBLK][T_FULL];
__device__ int   g_cidx[N_B][NBLK][T_FULL];

__device__ __forceinline__ float gfun(int j, float w) {
    float r = (float)j * 0.0625f;                 // j/16
    float l = fmaf((float)j, -0.03125f, 1.5f * w); // 1.5w - j/32
    return fmaxf(0.0f, fminf(r, l));
}

// ---- Precompute 5 second-difference deposits per (i, n) from weight ----
__global__ void prep_kernel(const float* __restrict__ w) {
    int idx = blockIdx.x * blockDim.x + threadIdx.x;
    if (idx >= N_CH * N_NEU) return;
    int n = idx & (N_NEU - 1);
    int i = idx >> 10;
    float wv = w[n * N_CH + i];
    int a = (int)floorf(16.0f * wv);
    int b = (int)floorf(48.0f * wv);
    int p[5] = {0, a, a + 1, b, b + 1};
    float d[5];
    bool dup[5];
    #pragma unroll
    for (int k = 0; k < 5; k++) {
        dup[k] = false;
        for (int m = 0; m < k; m++) if (p[m] == p[k]) dup[k] = true;
        d[k] = dup[k] ? 0.0f
                      : (gfun(p[k] + 1, wv) - 2.0f * gfun(p[k], wv) + gfun(p[k] - 1, wv));
    }
    // force exact zero slope after support (telescoping is exact in math;
    // make it exact in fp so the scan doesn't drift)
    int last = 0;
    #pragma unroll
    for (int k = 0; k < 5; k++) if (!dup[k]) last = k;
    float s = 0.0f;
    #pragma unroll
    for (int k = 0; k < 5; k++) if (k != last) s += d[k];
    d[last] = -s;
    #pragma unroll
    for (int k = 0; k < 5; k++) g_pd[k][idx] = d[k];
    g_pp[idx] = (a * NC) | ((b * NC) << 16);
}

// ---- Build per-(batch, ts-chunk) spike lists, sorted by (i, ts) ----
__global__ void spikes_kernel(const float* __restrict__ x) {
    int b = blockIdx.y, c = blockIdx.x, lane = threadIdx.x;
    const float* xb = x + (size_t)b * N_CH * T_IN;
    int cnt = 0;
    for (int m = 0; m < (N_CH * 64) / 32; m++) {
        int e = m * 32 + lane;
        int i = e >> 6;
        int ts = c * 64 + (e & 63);
        bool sp = xb[i * T_IN + ts] != 0.0f;
        unsigned mm = __ballot_sync(0xffffffffu, sp);
        if (sp) {
            int ofs = cnt + __popc(mm & ((1u << lane) - 1u));
            if (ofs < CAP) g_spk[b][c][ofs] = (i << 9) | ts;
        }
        cnt += __popc(mm);
    }
    if (lane == 0) g_scnt[b][c] = min(cnt, CAP);
}

// ---- Main: scatter deposits, double-scan, per-t argmax candidates ----
// Block = (batch b, neuron-chunk nb). 256 threads: warp = slot(=ts-chunk),
// lane = local neuron (= smem bank owner -> all scatters conflict-free).
__global__ void __launch_bounds__(256, 2) pot_kernel() {
    extern __shared__ float D[];          // [DW][NC] = 564*32 floats (72 KB)
    __shared__ float sA[NCHUNK * NC];
    __shared__ float sB[NCHUNK * NC];

    const int b = blockIdx.y, nb = blockIdx.x;
    const int tid = threadIdx.x;
    const int slot = tid >> 5;            // 0..7
    const int lane = tid & 31;            // local neuron
    const int n_glob = nb * NC + lane;

    for (int u = tid; u < DW * NC; u += 256) D[u] = 0.0f;
    __syncthreads();

    // Phase 1/2: deposits, 2-color over ts-chunk parity (span 113 < 128)
    for (int par = 0; par < 2; par++) {
        if ((slot & 1) == par) {
            const int cnt = g_scnt[b][slot];
            const int* __restrict__ lst = g_spk[b][slot];
            float* Dl = D + lane;
            int cur_i = -1;
            float d0 = 0, d1 = 0, d2 = 0, d3 = 0, d4 = 0;
            int oa = 0, ob = 0;
            for (int s = 0; s < cnt; s++) {
                int u = lst[s];
                int i = u >> 9, ts = u & 511;
                if (i != cur_i) {
                    cur_i = i;
                    int pidx = i * N_NEU + n_glob;
                    d0 = g_pd[0][pidx]; d1 = g_pd[1][pidx]; d2 = g_pd[2][pidx];
                    d3 = g_pd[3][pidx]; d4 = g_pd[4][pidx];
                    int pp = g_pp[pidx];
                    oa = pp & 0xffff; ob = pp >> 16;     // a*32, b*32
                }
                float* p = Dl + ts * NC;                 // bank = lane, always
                p[0]       += d0;
                p[oa]      += d1;
                p[oa + NC] += d2;
                p[ob]      += d3;
                p[ob + NC] += d4;
            }
        }
        __syncthreads();
    }

    // Double cumulative sum over t per neuron, split into 8 segments/neuron.
    {
        const int u0 = slot * SEGL;
        const int u1 = min(u0 + SEGL, DW);
        float a = 0.0f, v = 0.0f;
        for (int u = u0; u < u1; u++) { a += D[u * NC + lane]; v += a; }
        sA[slot * NC + lane] = a;
        sB[slot * NC + lane] = v;
        __syncthreads();
        float s = 0.0f, vin = 0.0f;
        for (int m = 0; m < slot; m++) {
            vin += (float)SEGL * s + sB[m * NC + lane];
            s   += sA[m * NC + lane];
        }
        for (int u = u0; u < u1; u++) {
            s += D[u * NC + lane];
            vin += s;
            D[u * NC + lane] = vin;                       // pot at t = u - 14
        }
        __syncthreads();
    }

    // Per-t argmax over this block's 32 neurons (staggered n to avoid conflicts)
    for (int t = tid; t < T_FULL; t += 256) {
        const float* row = D + (t + 14) * NC;
        float bv = -1e30f; int bi = 0;
        #pragma unroll
        for (int j = 0; j < NC; j++) {
            int nl = (j + lane) & 31;
            float v = row[nl];
            if (v > bv || (v == bv && nl < bi)) { bv = v; bi = nl; }
        }
        g_cval[b][nb][t] = bv;
        g_cidx[b][nb][t] = nb * NC + bi;
    }
}

// ---- Reduce candidates + sequential WTA (depression uniform per batch) ----
__global__ void wta_kernel(float* __restrict__ out) {
    __shared__ float sv[T_FULL];
    __shared__ int   si[T_FULL];
    int b = blockIdx.x, tid = threadIdx.x;
    if (tid < T_FULL) {
        float bv = -1e30f; int bi = 0;
        for (int c = 0; c < NBLK; c++) {
            float v = g_cval[b][c][tid];
            int  ix = g_cidx[b][c][tid];
            if (v > bv || (v == bv && ix < bi)) { bv = v; bi = ix; }
        }
        sv[tid] = bv + BIASV;
        si[tid] = bi;
    }
    __syncthreads();
    if (tid == 0) {
        float* ob = out + (size_t)b * N_NEU * T_FULL;
        int skip = 0;
        for (int t = 0; t < T_FULL; t++) {
            if (skip > 0) { skip--; continue; }
            if (sv[t] > THETA) {
                ob[(size_t)si[t] * T_FULL + t] = 1.0f;
                skip = 47;                 // clip(dep+48-1, 0, 47)
            }
        }
    }
}

extern "C" void kernel_launch(void* const* d_in, const int* in_sizes, int n_in,
                              void* d_out, int out_size) {
    const float* x;
    const float* w;
    if (in_sizes[0] == N_B * N_CH * T_IN) { x = (const float*)d_in[0]; w = (const float*)d_in[1]; }
    else                                  { x = (const float*)d_in[1]; w = (const float*)d_in[0]; }
    float* out = (float*)d_out;

    cudaFuncSetAttribute(pot_kernel, cudaFuncAttributeMaxDynamicSharedMemorySize,
                         DW * NC * (int)sizeof(float));

    cudaMemsetAsync(d_out, 0, (size_t)out_size * sizeof(float), 0);
    prep_kernel<<<(N_CH * N_NEU + 255) / 256, 256>>>(w);
    spikes_kernel<<<dim3(NCHUNK, N_B), 32>>>(x);
    pot_kernel<<<dim3(NBLK, N_B), 256, DW * NC * (int)sizeof(float)>>>();
    wta_kernel<<<N_B, 544>>>(out);
}

// round 3
// speedup vs baseline: 3.5236x; 1.3866x over previous
#include <cuda_runtime.h>

#define T_FULL 529
#define N_NEU  1024
#define N_CH   512
#define T_IN   512
#define N_B    16
#define THETA  25.6f
#define BIASV  12.8f

#define NCHUNK 8           // ts chunks of 64
#define NSEG   8           // channel segments per chunk (64 channels each)
#define SEGCAP 512         // max spikes per (b,chunk,seg); expected ~205
#define RUNCAP 64          // max runs per (b,chunk,seg) = 64 channels
#define NC     32          // neurons per block (= #banks -> conflict-free scatter)
#define NBLK   (N_NEU/NC)  // 32
#define DW     564         // deposit array length over u (need >= 561)
#define SEGL   71          // scan segment length (8*71 >= 564)

// run-encoded spike lists
__device__ unsigned char  g_ts[N_B][NCHUNK][NSEG][SEGCAP];   // dts in [0,64)
__device__ unsigned short g_runs[N_B][NCHUNK][NSEG][RUNCAP]; // (i<<6)|(cnt-1)
__device__ int            g_rcnt[N_B][NCHUNK][NSEG];

// packed per-(i,n) deposit data
__device__ float4 g_p4[N_CH * N_NEU];   // d1,d2,d3,d4
__device__ float2 g_p2[N_CH * N_NEU];   // d0, __int_as_float(a*32 | (b*32)<<16)

__device__ float g_cval[N_B][NBLK][T_FULL];
__device__ int   g_cidx[N_B][NBLK][T_FULL];

__device__ __forceinline__ float gfun(int j, float w) {
    float r = (float)j * 0.0625f;                  // j/16
    float l = fmaf((float)j, -0.03125f, 1.5f * w); // 1.5w - j/32
    return fmaxf(0.0f, fminf(r, l));
}

// ---- Precompute 5 second-difference deposits per (i, n) from weight ----
__global__ void prep_kernel(const float* __restrict__ w) {
    int idx = blockIdx.x * blockDim.x + threadIdx.x;
    if (idx >= N_CH * N_NEU) return;
    int n = idx & (N_NEU - 1);
    int i = idx >> 10;
    float wv = w[n * N_CH + i];
    int a = (int)floorf(16.0f * wv);
    int b = (int)floorf(48.0f * wv);
    int p[5] = {0, a, a + 1, b, b + 1};
    float d[5];
    bool dup[5];
    #pragma unroll
    for (int k = 0; k < 5; k++) {
        dup[k] = false;
        for (int m = 0; m < k; m++) if (p[m] == p[k]) dup[k] = true;
        d[k] = dup[k] ? 0.0f
                      : (gfun(p[k] + 1, wv) - 2.0f * gfun(p[k], wv) + gfun(p[k] - 1, wv));
    }
    // force exact-zero slope after support so the scan doesn't drift
    int last = 0;
    #pragma unroll
    for (int k = 0; k < 5; k++) if (!dup[k]) last = k;
    float s = 0.0f;
    #pragma unroll
    for (int k = 0; k < 5; k++) if (k != last) s += d[k];
    d[last] = -s;
    g_p4[idx] = make_float4(d[1], d[2], d[3], d[4]);
    int pp = (a * NC) | ((b * NC) << 16);
    g_p2[idx] = make_float2(d[0], __int_as_float(pp));
}

// ---- Build run-encoded spike lists. Block = (chunk, batch), warp = channel seg ----
__global__ void __launch_bounds__(256) spikes_kernel(const float* __restrict__ x) {
    int b = blockIdx.y, c = blockIdx.x;
    int wid = threadIdx.x >> 5, lane = threadIdx.x & 31;
    const float* xb = x + (size_t)b * N_CH * T_IN + c * 64;
    int cnt = 0, nr = 0;
    for (int ic = 0; ic < 64; ic++) {
        int i = wid * 64 + ic;
        const float* row = xb + i * T_IN;
        bool f0 = row[lane] != 0.0f;
        bool f1 = row[32 + lane] != 0.0f;
        unsigned m0 = __ballot_sync(0xffffffffu, f0);
        unsigned m1 = __ballot_sync(0xffffffffu, f1);
        int tot = __popc(m0) + __popc(m1);
        if (tot > 0 && cnt + tot <= SEGCAP && nr < RUNCAP) {
            if (f0) g_ts[b][c][wid][cnt + __popc(m0 & ((1u << lane) - 1u))] =
                        (unsigned char)lane;
            if (f1) g_ts[b][c][wid][cnt + __popc(m0) + __popc(m1 & ((1u << lane) - 1u))] =
                        (unsigned char)(32 + lane);
            if (lane == 0) g_runs[b][c][wid][nr] = (unsigned short)((i << 6) | (tot - 1));
            nr++; cnt += tot;
        }
    }
    if (lane == 0) g_rcnt[b][c][wid] = nr;
}

// ---- Main: scatter deposits, double-scan, per-t argmax candidates ----
// Block = (batch b, neuron-chunk nb). 256 threads: warp = ts-chunk, lane = local
// neuron (= smem bank owner -> all scatters conflict-free).
__global__ void __launch_bounds__(256) pot_kernel() {
    extern __shared__ float D[];                              // [DW][NC] = 72 KB
    __shared__ __align__(16) unsigned char  s_ts[4][NSEG][SEGCAP];   // 16 KB
    __shared__ __align__(16) unsigned short s_rn[4][NSEG][RUNCAP];   // 4 KB
    __shared__ int   s_rc[4][NSEG];
    __shared__ float sA[NCHUNK * NC];
    __shared__ float sB[NCHUNK * NC];

    const int b = blockIdx.y, nb = blockIdx.x;
    const int tid = threadIdx.x;
    const int slot = tid >> 5;            // 0..7 = ts chunk
    const int lane = tid & 31;            // local neuron
    const int n_glob = nb * NC + lane;

    {
        int4* Dz = (int4*)D;
        for (int u = tid; u < DW * NC / 4; u += 256) Dz[u] = make_int4(0, 0, 0, 0);
    }
    __syncthreads();

    // Phase 1/2: deposits, 2-color over ts-chunk parity (span 113 < 128)
    for (int par = 0; par < 2; par++) {
        // stage this color's 4 chunks of list data into smem (bulk int4 copies)
        #pragma unroll
        for (int j = 0; j < 4; j++) {
            int c = 2 * j + par;
            ((int4*)s_ts[j])[tid] = ((const int4*)g_ts[b][c])[tid];       // 4 KB
            if (tid < 64) ((int4*)s_rn[j])[tid] = ((const int4*)g_runs[b][c])[tid];
            if (tid < NSEG) s_rc[j][tid] = g_rcnt[b][c][tid];
        }
        __syncthreads();

        if ((slot & 1) == par) {
            const int j = slot >> 1;
            float* Dl = D + lane + slot * 64 * NC;
            for (int seg = 0; seg < NSEG; seg++) {
                const int nr = s_rc[j][seg];
                const unsigned short* rn = s_rn[j][seg];
                const unsigned char*  tl = s_ts[j][seg];
                int pos = 0;
                int r = 0;
                while (r < nr) {
                    const int nb4 = min(4, nr - r);
                    float4 q4[4]; float2 q2[4]; int qn[4];
                    #pragma unroll
                    for (int k = 0; k < 4; k++) {
                        if (k < nb4) {
                            int rv  = rn[r + k];
                            qn[k]   = (rv & 63) + 1;
                            int idx = ((rv >> 6) << 10) + n_glob;
                            q4[k] = g_p4[idx];
                            q2[k] = g_p2[idx];
                        }
                    }
                    #pragma unroll
                    for (int k = 0; k < 4; k++) {
                        if (k < nb4) {
                            int pp = __float_as_int(q2[k].y);
                            int oa = pp & 0xffff, ob = pp >> 16;
                            float d0 = q2[k].x;
                            float d1 = q4[k].x, d2 = q4[k].y, d3 = q4[k].z, d4 = q4[k].w;
                            for (int s = 0; s < qn[k]; s++) {
                                int dts = tl[pos++];
                                float* p = Dl + dts * NC;    // bank = lane, always
                                p[0]       += d0;
                                p[oa]      += d1;
                                p[oa + NC] += d2;
                                p[ob]      += d3;
                                p[ob + NC] += d4;
                            }
                        }
                    }
                    r += nb4;
                }
            }
        }
        __syncthreads();
    }

    // Double cumulative sum over u per neuron, split into 8 segments/neuron.
    {
        const int u0 = slot * SEGL;
        const int u1 = min(u0 + SEGL, DW);
        float a = 0.0f, v = 0.0f;
        for (int u = u0; u < u1; u++) { a += D[u * NC + lane]; v += a; }
        sA[slot * NC + lane] = a;
        sB[slot * NC + lane] = v;
        __syncthreads();
        float s = 0.0f, vin = 0.0f;
        for (int m = 0; m < slot; m++) {
            vin += (float)SEGL * s + sB[m * NC + lane];
            s   += sA[m * NC + lane];
        }
        for (int u = u0; u < u1; u++) {
            s += D[u * NC + lane];
            vin += s;
            D[u * NC + lane] = vin;                       // pot at t = u - 14
        }
        __syncthreads();
    }

    // Per-t argmax over this block's 32 neurons (staggered n to avoid conflicts)
    for (int t = tid; t < T_FULL; t += 256) {
        const float* row = D + (t + 14) * NC;
        float bv = -1e30f; int bi = 0;
        #pragma unroll
        for (int j = 0; j < NC; j++) {
            int nl = (j + lane) & 31;
            float v = row[nl];
            if (v > bv || (v == bv && nl < bi)) { bv = v; bi = nl; }
        }
        g_cval[b][nb][t] = bv;
        g_cidx[b][nb][t] = nb * NC + bi;
    }
}

// ---- Reduce candidates + sequential WTA (depression uniform per batch) ----
__global__ void wta_kernel(float* __restrict__ out) {
    __shared__ float sv[T_FULL];
    __shared__ int   si[T_FULL];
    int b = blockIdx.x, tid = threadIdx.x;
    if (tid < T_FULL) {
        float bv = -1e30f; int bi = 0;
        #pragma unroll 8
        for (int c = 0; c < NBLK; c++) {
            float v = g_cval[b][c][tid];
            int  ix = g_cidx[b][c][tid];
            if (v > bv || (v == bv && ix < bi)) { bv = v; bi = ix; }
        }
        sv[tid] = bv + BIASV;
        si[tid] = bi;
    }
    __syncthreads();
    if (tid == 0) {
        float* ob = out + (size_t)b * N_NEU * T_FULL;
        int skip = 0;
        for (int t = 0; t < T_FULL; t++) {
            if (skip > 0) { skip--; continue; }
            if (sv[t] > THETA) {
                ob[(size_t)si[t] * T_FULL + t] = 1.0f;
                skip = 47;                 // clip(dep+48-1, 0, 47)
            }
        }
    }
}

extern "C" void kernel_launch(void* const* d_in, const int* in_sizes, int n_in,
                              void* d_out, int out_size) {
    const float* x;
    const float* w;
    if (in_sizes[0] == N_B * N_CH * T_IN) { x = (const float*)d_in[0]; w = (const float*)d_in[1]; }
    else                                  { x = (const float*)d_in[1]; w = (const float*)d_in[0]; }
    float* out = (float*)d_out;

    cudaFuncSetAttribute(pot_kernel, cudaFuncAttributeMaxDynamicSharedMemorySize,
                         DW * NC * (int)sizeof(float));

    cudaMemsetAsync(d_out, 0, (size_t)out_size * sizeof(float), 0);
    prep_kernel<<<(N_CH * N_NEU + 255) / 256, 256>>>(w);
    spikes_kernel<<<dim3(NCHUNK, N_B), 256>>>(x);
    pot_kernel<<<dim3(NBLK, N_B), 256, DW * NC * (int)sizeof(float)>>>();
    wta_kernel<<<N_B, 544>>>(out);
}

// round 4
// speedup vs baseline: 4.4812x; 1.2718x over previous
#include <cuda_runtime.h>

#define T_FULL 529
#define N_NEU  1024
#define N_CH   512
#define T_IN   512
#define N_B    16
#define THETA  25.6f
#define BIASV  12.8f

#define NCHUNK 8           // ts chunks of 64
#define NSEG   8           // channel segments per chunk (64 channels each)
#define SEGCAP 640         // padded bytes per (b,chunk,seg); expected ~390
#define RUNCAP 64          // max runs per (b,chunk,seg) = 64 channels
#define NC     32          // neurons per block (= #banks -> conflict-free scatter)
#define NBLK   (N_NEU/NC)  // 32
#define DW     568         // deposit length over u (needs >= 512+53+1; 8*71)
#define SEGL   71          // scan segment length

// run-encoded spike lists (ts bytes; each run starts 4-aligned)
__device__ unsigned char  g_ts[N_B][NCHUNK][NSEG][SEGCAP];
__device__ unsigned short g_runs[N_B][NCHUNK][NSEG][RUNCAP]; // (i<<6)|(cnt-1)
__device__ int            g_rcnt[N_B][NCHUNK][NSEG];

// packed per-(i,n) deposit data
__device__ float4 g_p4[N_CH * N_NEU];   // d1,d2,d3,d4
__device__ float2 g_p2[N_CH * N_NEU];   // d0, __int_as_float(p1|p2<<8|p3<<16|p4<<24)

__device__ float g_cval[N_B][NBLK][T_FULL];
__device__ int   g_cidx[N_B][NBLK][T_FULL];

__device__ __forceinline__ float gfun(int j, float w) {
    float r = (float)j * 0.0625f;                  // j/16
    float l = fmaf((float)j, -0.03125f, 1.5f * w); // 1.5w - j/32
    return fmaxf(0.0f, fminf(r, l));
}

// ---- Precompute 5 second-difference deposits per (i, n); positions made
// pairwise-distinct (dups -> dummy slots 50.. with d=0) so the RMW can batch.
__global__ void prep_kernel(const float* __restrict__ w) {
    int idx = blockIdx.x * blockDim.x + threadIdx.x;
    if (idx >= N_CH * N_NEU) return;
    int n = idx & (N_NEU - 1);
    int i = idx >> 10;
    float wv = w[n * N_CH + i];
    int a = (int)floorf(16.0f * wv);
    int b = (int)floorf(48.0f * wv);
    int p[5] = {0, a, a + 1, b, b + 1};
    float d[5];
    bool dup[5];
    #pragma unroll
    for (int k = 0; k < 5; k++) {
        dup[k] = false;
        #pragma unroll
        for (int m = 0; m < 5; m++)
            if (m < k && p[m] == p[k]) dup[k] = true;
        d[k] = dup[k] ? 0.0f
                      : (gfun(p[k] + 1, wv) - 2.0f * gfun(p[k], wv) + gfun(p[k] - 1, wv));
    }
    // exact-zero total so the double-scan doesn't drift past support
    int last = 0;
    #pragma unroll
    for (int k = 0; k < 5; k++) if (!dup[k]) last = k;
    float s = 0.0f;
    #pragma unroll
    for (int k = 0; k < 5; k++) if (k != last) s += d[k];
    d[last] = -s;
    // reassign duplicate positions to distinct dummies (write 0.0 there)
    int dummy = 50;
    #pragma unroll
    for (int k = 0; k < 5; k++) if (dup[k]) p[k] = dummy++;
    g_p4[idx] = make_float4(d[1], d[2], d[3], d[4]);
    int pp = p[1] | (p[2] << 8) | (p[3] << 16) | (p[4] << 24);
    g_p2[idx] = make_float2(d[0], __int_as_float(pp));
}

// ---- Build run-encoded spike lists; each run's ts bytes start 4-aligned ----
__global__ void __launch_bounds__(256) spikes_kernel(const float* __restrict__ x) {
    int b = blockIdx.y, c = blockIdx.x;
    int wid = threadIdx.x >> 5, lane = threadIdx.x & 31;
    const float* xb = x + (size_t)b * N_CH * T_IN + c * 64;
    int cnt = 0, nr = 0;
    for (int ic = 0; ic < 64; ic++) {
        int i = wid * 64 + ic;
        const float* row = xb + i * T_IN;
        bool f0 = row[lane] != 0.0f;
        bool f1 = row[32 + lane] != 0.0f;
        unsigned m0 = __ballot_sync(0xffffffffu, f0);
        unsigned m1 = __ballot_sync(0xffffffffu, f1);
        int tot = __popc(m0) + __popc(m1);
        if (tot > 0 && cnt + tot <= SEGCAP && nr < RUNCAP) {
            if (f0) g_ts[b][c][wid][cnt + __popc(m0 & ((1u << lane) - 1u))] =
                        (unsigned char)lane;
            if (f1) g_ts[b][c][wid][cnt + __popc(m0) + __popc(m1 & ((1u << lane) - 1u))] =
                        (unsigned char)(32 + lane);
            if (lane == 0) g_runs[b][c][wid][nr] = (unsigned short)((i << 6) | (tot - 1));
            nr++;
            cnt = (cnt + tot + 3) & ~3;     // keep next run 4-aligned
        }
    }
    if (lane == 0) g_rcnt[b][c][wid] = nr;
}

// 5-point batched RMW: positions guaranteed distinct -> 5 LDS, 5 FADD, 5 STS
#define DEPOSIT(dts_)                                                    \
    do {                                                                 \
        float* base = Dl + (int)(dts_) * NC;                             \
        float v0 = base[0],  v1 = base[o1], v2 = base[o2];               \
        float v3 = base[o3], v4 = base[o4];                              \
        base[0]  = v0 + d0; base[o1] = v1 + d1; base[o2] = v2 + d2;      \
        base[o3] = v3 + d3; base[o4] = v4 + d4;                          \
    } while (0)

// ---- Main: scatter deposits, double-scan, per-t argmax candidates ----
// Block = (batch b, neuron-chunk nb). 256 threads: warp = ts-chunk, lane = local
// neuron (= smem bank owner -> all scatters conflict-free).
__global__ void __launch_bounds__(256) pot_kernel() {
    extern __shared__ float D[];                                 // [DW][NC] 72.7 KB
    __shared__ __align__(16) unsigned char  s_ts[4][NSEG][SEGCAP];   // 20 KB
    __shared__ __align__(16) unsigned short s_rn[4][NSEG][RUNCAP];   // 4 KB
    __shared__ int   s_rc[4][NSEG];
    __shared__ float sA[NCHUNK * NC];
    __shared__ float sB[NCHUNK * NC];

    const int b = blockIdx.y, nb = blockIdx.x;
    const int tid = threadIdx.x;
    const int slot = tid >> 5;            // 0..7 = ts chunk
    const int lane = tid & 31;            // local neuron
    const int n_glob = nb * NC + lane;

    {
        int4* Dz = (int4*)D;
        for (int u = tid; u < DW * NC / 4; u += 256) Dz[u] = make_int4(0, 0, 0, 0);
    }
    __syncthreads();

    // Phase 1/2: deposits, 2-color over ts-chunk parity (span 117 < 128)
    for (int par = 0; par < 2; par++) {
        // stage this color's 4 chunks of list data into smem
        #pragma unroll
        for (int j = 0; j < 4; j++) {
            int c = 2 * j + par;
            for (int u = tid; u < NSEG * SEGCAP / 16; u += 256)
                ((int4*)s_ts[j])[u] = ((const int4*)g_ts[b][c])[u];
            if (tid < NSEG * RUNCAP * 2 / 16)
                ((int4*)s_rn[j])[tid] = ((const int4*)g_runs[b][c])[tid];
            if (tid < NSEG) s_rc[j][tid] = g_rcnt[b][c][tid];
        }
        __syncthreads();

        if ((slot & 1) == par) {
            const int j = slot >> 1;
            float* Dl = D + lane + slot * 64 * NC;
            for (int seg = 0; seg < NSEG; seg++) {
                const int nr = s_rc[j][seg];
                const unsigned short* rn = s_rn[j][seg];
                const unsigned char*  tl = s_ts[j][seg];
                int pos = 0;
                int r = 0;
                while (r < nr) {
                    const int nb4 = min(4, nr - r);
                    float4 q4[4]; float2 q2[4]; int qn[4];
                    #pragma unroll
                    for (int k = 0; k < 4; k++) {
                        if (k < nb4) {
                            int rv  = rn[r + k];
                            qn[k]   = (rv & 63) + 1;
                            int idx = ((rv >> 6) << 10) + n_glob;
                            q4[k] = g_p4[idx];
                            q2[k] = g_p2[idx];
                        }
                    }
                    #pragma unroll
                    for (int k = 0; k < 4; k++) {
                        if (k < nb4) {
                            const int pp = __float_as_int(q2[k].y);
                            const int o1 = (pp & 0xff) * NC;
                            const int o2 = ((pp >> 8) & 0xff) * NC;
                            const int o3 = ((pp >> 16) & 0xff) * NC;
                            const int o4 = ((pp >> 24) & 0xff) * NC;
                            const float d0 = q2[k].x;
                            const float d1 = q4[k].x, d2 = q4[k].y;
                            const float d3 = q4[k].z, d4 = q4[k].w;
                            const int cnt = qn[k];
                            const int nfull = cnt >> 2;
                            for (int wq = 0; wq < nfull; wq++) {
                                unsigned tsw = *(const unsigned*)(tl + pos);
                                pos += 4;
                                DEPOSIT(tsw & 0xffu);
                                DEPOSIT((tsw >> 8) & 0xffu);
                                DEPOSIT((tsw >> 16) & 0xffu);
                                DEPOSIT(tsw >> 24);
                            }
                            const int rem = cnt & 3;
                            if (rem) {
                                unsigned tsw = *(const unsigned*)(tl + pos);
                                pos += 4;
                                DEPOSIT(tsw & 0xffu);
                                if (rem > 1) DEPOSIT((tsw >> 8) & 0xffu);
                                if (rem > 2) DEPOSIT((tsw >> 16) & 0xffu);
                            }
                        }
                    }
                    r += nb4;
                }
            }
        }
        __syncthreads();
    }

    // Double cumulative sum over u per neuron, split into 8 segments/neuron.
    {
        const int u0 = slot * SEGL;
        const int u1 = u0 + SEGL;
        float a = 0.0f, v = 0.0f;
        for (int u = u0; u < u1; u++) { a += D[u * NC + lane]; v += a; }
        sA[slot * NC + lane] = a;
        sB[slot * NC + lane] = v;
        __syncthreads();
        float s = 0.0f, vin = 0.0f;
        for (int m = 0; m < slot; m++) {
            vin += (float)SEGL * s + sB[m * NC + lane];
            s   += sA[m * NC + lane];
        }
        for (int u = u0; u < u1; u++) {
            s += D[u * NC + lane];
            vin += s;
            D[u * NC + lane] = vin;                       // pot at t = u - 14
        }
        __syncthreads();
    }

    // Per-t argmax over this block's 32 neurons (staggered n to avoid conflicts)
    for (int t = tid; t < T_FULL; t += 256) {
        const float* row = D + (t + 14) * NC;
        float bv = -1e30f; int bi = 0;
        #pragma unroll
        for (int j = 0; j < NC; j++) {
            int nl = (j + lane) & 31;
            float v = row[nl];
            if (v > bv || (v == bv && nl < bi)) { bv = v; bi = nl; }
        }
        g_cval[b][nb][t] = bv;
        g_cidx[b][nb][t] = nb * NC + bi;
    }
}

// ---- Reduce candidates + sequential WTA (depression uniform per batch) ----
__global__ void wta_kernel(float* __restrict__ out) {
    __shared__ float sv[T_FULL];
    __shared__ int   si[T_FULL];
    int b = blockIdx.x, tid = threadIdx.x;
    if (tid < T_FULL) {
        float bv = -1e30f; int bi = 0;
        #pragma unroll 8
        for (int c = 0; c < NBLK; c++) {
            float v = g_cval[b][c][tid];
            int  ix = g_cidx[b][c][tid];
            if (v > bv || (v == bv && ix < bi)) { bv = v; bi = ix; }
        }
        sv[tid] = bv + BIASV;
        si[tid] = bi;
    }
    __syncthreads();
    if (tid == 0) {
        float* ob = out + (size_t)b * N_NEU * T_FULL;
        int skip = 0;
        for (int t = 0; t < T_FULL; t++) {
            if (skip > 0) { skip--; continue; }
            if (sv[t] > THETA) {
                ob[(size_t)si[t] * T_FULL + t] = 1.0f;
                skip = 47;                 // clip(dep+48-1, 0, 47)
            }
        }
    }
}

extern "C" void kernel_launch(void* const* d_in, const int* in_sizes, int n_in,
                              void* d_out, int out_size) {
    const float* x;
    const float* w;
    if (in_sizes[0] == N_B * N_CH * T_IN) { x = (const float*)d_in[0]; w = (const float*)d_in[1]; }
    else                                  { x = (const float*)d_in[1]; w = (const float*)d_in[0]; }
    float* out = (float*)d_out;

    cudaFuncSetAttribute(pot_kernel, cudaFuncAttributeMaxDynamicSharedMemorySize,
                         DW * NC * (int)sizeof(float));

    cudaMemsetAsync(d_out, 0, (size_t)out_size * sizeof(float), 0);
    prep_kernel<<<(N_CH * N_NEU + 255) / 256, 256>>>(w);
    spikes_kernel<<<dim3(NCHUNK, N_B), 256>>>(x);
    pot_kernel<<<dim3(NBLK, N_B), 256, DW * NC * (int)sizeof(float)>>>();
    wta_kernel<<<N_B, 544>>>(out);
}